// round 1
// baseline (speedup 1.0000x reference)
#include <cuda_runtime.h>
#include <math.h>

#define NB 128
#define DD 192
#define DEPTHL 12
#define NHD 3
#define HDIM 64
#define NE 4
#define NT 65
#define NTP 66
#define NCLS 100
#define DH 384
#define CHK 22
#define NCHUNK 3
#define NTHR 192

struct __align__(16) SM {
    float t[NTP * DD];
    float Y[NTP * DD];
    float S[NTP * DH];   // per-head QKV (first half) + attn out O (second half); MoE hidden H spans both
    float m[NTP];
    float rs[NTP];
    float gl[NTP * NE];
    float selw[NTP * 2];
    float ewt[NE * 72];
    int   seli[NTP * 2];
    int   elist[NE * 72];
    int   ecnt[NE];
};

__device__ __forceinline__ float gelu_exact(float x) {
    return 0.5f * x * (1.0f + erff(x * 0.70710678118654752f));
}

__device__ __forceinline__ float dot4(float4 a, float4 b) {
    return a.x * b.x + a.y * b.y + a.z * b.z + a.w * b.w;
}

__device__ __forceinline__ void ln_stats(const float* __restrict__ base, int n0, int n1,
                                         float* __restrict__ m, float* __restrict__ rs) {
    int warp = threadIdx.x >> 5, lane = threadIdx.x & 31;
    for (int n = n0 + warp; n < n1; n += 6) {
        const float* row = base + n * DD;
        float s = 0.f;
        for (int c = lane; c < DD; c += 32) s += row[c];
#pragma unroll
        for (int o = 16; o; o >>= 1) s += __shfl_xor_sync(0xffffffffu, s, o);
        float mm = s * (1.0f / DD);
        float q = 0.f;
        for (int c = lane; c < DD; c += 32) { float d = row[c] - mm; q += d * d; }
#pragma unroll
        for (int o = 16; o; o >>= 1) q += __shfl_xor_sync(0xffffffffu, q, o);
        if (lane == 0) { m[n] = mm; rs[n] = rsqrtf(q * (1.0f / DD) + 1e-5f); }
    }
}

__global__ void __launch_bounds__(NTHR, 1) hypervit_kernel(
    const float* __restrict__ x, const float* __restrict__ conv_w, const float* __restrict__ conv_b,
    const float* __restrict__ pe_g, const float* __restrict__ pe_b,
    const float* __restrict__ cls_token, const float* __restrict__ pos_embed,
    const float* __restrict__ n1_g, const float* __restrict__ n1_b,
    const float* __restrict__ qkv_w, const float* __restrict__ temp,
    const float* __restrict__ proj_w, const float* __restrict__ proj_b,
    const float* __restrict__ n2_g, const float* __restrict__ n2_b,
    const float* __restrict__ gate_w, const float* __restrict__ gate_b,
    const float* __restrict__ e_w1, const float* __restrict__ e_b1,
    const float* __restrict__ e_w2, const float* __restrict__ e_b2,
    const float* __restrict__ attn_scale, const float* __restrict__ mlp_scale,
    const float* __restrict__ norm_g, const float* __restrict__ norm_b,
    const float* __restrict__ hc_w, const float* __restrict__ hc_b,
    const float* __restrict__ head_w, const float* __restrict__ head_b,
    float* __restrict__ out)
{
    extern __shared__ char smraw[];
    SM* sp = (SM*)smraw;
    const int b = blockIdx.x;
    const int tid = threadIdx.x;
    const int warp = tid >> 5, lane = tid & 31;
    float* t = sp->t;
    float* Y = sp->Y;
    float* S = sp->S;
    float* O = S + NTP * DD;

    // Clean scratch (pad rows read harmlessly later; keep them finite)
    for (int i = tid; i < NTP * DH; i += NTHR) S[i] = 0.f;

    // ======================= patch embed =======================
    {
        float* P = Y;  // 64 x 48
        for (int i = tid; i < 64 * 48; i += NTHR) {
            int patch = i / 48, f = i % 48;
            int c = f >> 4, pi = (f >> 2) & 3, pj = f & 3;
            int ph = patch >> 3, pw = patch & 7;
            P[i] = x[((b * 3 + c) * 32 + ph * 4 + pi) * 32 + pw * 4 + pj];
        }
        __syncthreads();
        {
            float wreg[48];
            const float* w = conv_w + tid * 48;
#pragma unroll
            for (int c = 0; c < 48; c++) wreg[c] = w[c];
            float cb = conv_b[tid];
            for (int p = 0; p < 64; p++) {
                float acc = cb;
#pragma unroll
                for (int c = 0; c < 48; c++) acc += P[p * 48 + c] * wreg[c];
                t[(p + 1) * DD + tid] = acc;
            }
        }
        __syncthreads();
        ln_stats(t, 1, 65, sp->m, sp->rs);
        __syncthreads();
        float g = pe_g[tid], bb = pe_b[tid];
        for (int n = 1; n < 65; n++)
            t[n * DD + tid] = (t[n * DD + tid] - sp->m[n]) * sp->rs[n] * g + bb + pos_embed[n * DD + tid];
        t[tid] = cls_token[tid] + pos_embed[tid];
        t[65 * DD + tid] = 0.f;
    }
    __syncthreads();

    // ======================= transformer layers =======================
    for (int l = 0; l < DEPTHL; l++) {
        // ---- LN1 -> Y ----
        ln_stats(t, 0, 65, sp->m, sp->rs);
        __syncthreads();
        {
            float g = n1_g[l * DD + tid], bb = n1_b[l * DD + tid];
            for (int n = 0; n < 65; n++)
                Y[n * DD + tid] = (t[n * DD + tid] - sp->m[n]) * sp->rs[n] * g + bb;
            Y[65 * DD + tid] = 0.f;
        }
        __syncthreads();

        const float asc = attn_scale[l];

        // ---- attention, per head ----
        for (int h = 0; h < NHD; h++) {
            // qkv GEMM for this head: thread tid owns output column tid of [q|k|v] (64 each)
            {
                int sec = tid >> 6, d = tid & 63;
                const float* w = qkv_w + ((size_t)l * 3 * DD + sec * DD + h * HDIM + d) * DD;
                for (int ch = 0; ch < NCHUNK; ch++) {
                    int n0 = ch * CHK;
                    float acc[CHK];
#pragma unroll
                    for (int nn = 0; nn < CHK; nn++) acc[nn] = 0.f;
                    for (int c = 0; c < DD; c += 4) {
                        float4 w4 = *(const float4*)(w + c);
#pragma unroll
                        for (int nn = 0; nn < CHK; nn++) {
                            float4 y4 = *(const float4*)(Y + (n0 + nn) * DD + c);
                            acc[nn] += dot4(y4, w4);
                        }
                    }
#pragma unroll
                    for (int nn = 0; nn < CHK; nn++) S[(n0 + nn) * DD + tid] = acc[nn];
                }
            }
            __syncthreads();

            // banded attention (|i-j| <= 3): one warp per row i
            {
                float coef = 0.125f / temp[l * NHD + h];
                for (int i = warp; i < 65; i += 6) {
                    int jlo = (i - 3 < 0) ? 0 : i - 3;
                    int jhi = (i + 3 > 64) ? 64 : i + 3;
                    int cnt = jhi - jlo + 1;
                    const float* q = S + i * DD;
                    float2 qv = *(const float2*)(q + 2 * lane);
                    float sc[7];
#pragma unroll
                    for (int jj = 0; jj < 7; jj++) {
                        if (jj < cnt) {
                            const float* k = S + (jlo + jj) * DD + 64;
                            float2 kv = *(const float2*)(k + 2 * lane);
                            float p = qv.x * kv.x + qv.y * kv.y;
#pragma unroll
                            for (int o = 16; o; o >>= 1) p += __shfl_xor_sync(0xffffffffu, p, o);
                            sc[jj] = p * coef;
                        }
                    }
                    float mx = sc[0];
#pragma unroll
                    for (int jj = 1; jj < 7; jj++) if (jj < cnt) mx = fmaxf(mx, sc[jj]);
                    float ssum = 0.f;
#pragma unroll
                    for (int jj = 0; jj < 7; jj++) if (jj < cnt) { sc[jj] = expf(sc[jj] - mx); ssum += sc[jj]; }
                    float inv = 1.0f / ssum;
                    float o0 = 0.f, o1 = 0.f;
#pragma unroll
                    for (int jj = 0; jj < 7; jj++) {
                        if (jj < cnt) {
                            const float* v = S + (jlo + jj) * DD + 128;
                            float2 vv = *(const float2*)(v + 2 * lane);
                            o0 += sc[jj] * vv.x;
                            o1 += sc[jj] * vv.y;
                        }
                    }
                    O[i * DD + h * HDIM + 2 * lane]     = o0 * inv;
                    O[i * DD + h * HDIM + 2 * lane + 1] = o1 * inv;
                }
            }
            __syncthreads();
        }

        // ---- proj + residual ----
        {
            const float* w = proj_w + ((size_t)l * DD + tid) * DD;
            float pb = proj_b[l * DD + tid];
            for (int ch = 0; ch < NCHUNK; ch++) {
                int n0 = ch * CHK;
                float acc[CHK];
#pragma unroll
                for (int nn = 0; nn < CHK; nn++) acc[nn] = 0.f;
                for (int c = 0; c < DD; c += 4) {
                    float4 w4 = *(const float4*)(w + c);
#pragma unroll
                    for (int nn = 0; nn < CHK; nn++) {
                        float4 o4 = *(const float4*)(O + (n0 + nn) * DD + c);
                        acc[nn] += dot4(o4, w4);
                    }
                }
#pragma unroll
                for (int nn = 0; nn < CHK; nn++)
                    t[(n0 + nn) * DD + tid] += asc * (acc[nn] + pb);
            }
        }
        __syncthreads();

        // ---- LN2 -> Y ----
        ln_stats(t, 0, 65, sp->m, sp->rs);
        __syncthreads();
        {
            float g = n2_g[l * DD + tid], bb = n2_b[l * DD + tid];
            for (int n = 0; n < 65; n++)
                Y[n * DD + tid] = (t[n * DD + tid] - sp->m[n]) * sp->rs[n] * g + bb;
            Y[65 * DD + tid] = 0.f;
        }
        __syncthreads();

        // ---- gating ----
        for (int task = tid; task < NT * NE; task += NTHR) {
            int n = task >> 2, e = task & 3;
            const float* gw = gate_w + ((size_t)l * NE + e) * DD;
            float acc = gate_b[l * NE + e];
            for (int c = 0; c < DD; c += 4) {
                float4 y4 = *(const float4*)(Y + n * DD + c);
                float4 w4 = *(const float4*)(gw + c);
                acc += dot4(y4, w4);
            }
            sp->gl[n * NE + e] = acc;
        }
        __syncthreads();
        if (tid < NT) {
            float v0 = sp->gl[tid * 4 + 0], v1 = sp->gl[tid * 4 + 1];
            float v2 = sp->gl[tid * 4 + 2], v3 = sp->gl[tid * 4 + 3];
            float vv[4] = { v0, v1, v2, v3 };
            int i0 = 0; float bmax = vv[0];
#pragma unroll
            for (int e = 1; e < 4; e++) if (vv[e] > bmax) { bmax = vv[e]; i0 = e; }
            int i1 = -1; float b2v = -1e30f;
#pragma unroll
            for (int e = 0; e < 4; e++) if (e != i0 && vv[e] > b2v) { b2v = vv[e]; i1 = e; }
            float w1 = expf(b2v - bmax);
            float inv = 1.0f / (1.0f + w1);
            sp->seli[tid * 2 + 0] = i0;
            sp->seli[tid * 2 + 1] = i1;
            sp->selw[tid * 2 + 0] = inv;
            sp->selw[tid * 2 + 1] = w1 * inv;
        }
        __syncthreads();
        if (tid == 0) {
            float msc = mlp_scale[l];
            int cnt[4] = { 0, 0, 0, 0 };
            for (int n = 0; n < NT; n++) {
                for (int sidx = 0; sidx < 2; sidx++) {
                    int e = sp->seli[n * 2 + sidx];
                    sp->elist[e * 72 + cnt[e]] = n;
                    sp->ewt[e * 72 + cnt[e]] = sp->selw[n * 2 + sidx] * msc;
                    cnt[e]++;
                }
            }
            for (int e = 0; e < 4; e++) {
                while (cnt[e] % CHK != 0) {
                    sp->elist[e * 72 + cnt[e]] = 65;  // dummy pad row
                    sp->ewt[e * 72 + cnt[e]] = 0.f;
                    cnt[e]++;
                }
                sp->ecnt[e] = cnt[e];
            }
        }
        __syncthreads();

        // ---- expert FFNs (token-grouped) ----
        float* Hb = S;  // [NTP][DH]
        for (int e = 0; e < NE; e++) {
            int cnt = sp->ecnt[e];
            int nch = cnt / CHK;
            if (nch == 0) continue;
            // GEMM1: Y[tok] @ w1^T -> H[tok][0..383], gelu
            {
                const float* w1base = e_w1 + (size_t)(l * NE + e) * DH * DD;
                const float* b1 = e_b1 + (size_t)(l * NE + e) * DH;
                for (int dd = 0; dd < 2; dd++) {
                    int dim = tid + dd * NTHR;
                    const float* w = w1base + (size_t)dim * DD;
                    float bias = b1[dim];
                    for (int ch = 0; ch < nch; ch++) {
                        int toks[CHK];
#pragma unroll
                        for (int nn = 0; nn < CHK; nn++) toks[nn] = sp->elist[e * 72 + ch * CHK + nn];
                        float acc[CHK];
#pragma unroll
                        for (int nn = 0; nn < CHK; nn++) acc[nn] = 0.f;
                        for (int c = 0; c < DD; c += 4) {
                            float4 w4 = *(const float4*)(w + c);
#pragma unroll
                            for (int nn = 0; nn < CHK; nn++) {
                                float4 y4 = *(const float4*)(Y + toks[nn] * DD + c);
                                acc[nn] += dot4(y4, w4);
                            }
                        }
#pragma unroll
                        for (int nn = 0; nn < CHK; nn++)
                            Hb[toks[nn] * DH + dim] = gelu_exact(acc[nn] + bias);
                    }
                }
            }
            __syncthreads();
            // GEMM2: H[tok] @ w2^T -> += t[tok]
            {
                const float* w = e_w2 + (size_t)(l * NE + e) * DD * DH + (size_t)tid * DH;
                float b2 = e_b2[(size_t)(l * NE + e) * DD + tid];
                for (int ch = 0; ch < nch; ch++) {
                    int toks[CHK];
                    float wt[CHK];
#pragma unroll
                    for (int nn = 0; nn < CHK; nn++) {
                        toks[nn] = sp->elist[e * 72 + ch * CHK + nn];
                        wt[nn] = sp->ewt[e * 72 + ch * CHK + nn];
                    }
                    float acc[CHK];
#pragma unroll
                    for (int nn = 0; nn < CHK; nn++) acc[nn] = 0.f;
                    for (int c = 0; c < DH; c += 4) {
                        float4 w4 = *(const float4*)(w + c);
#pragma unroll
                        for (int nn = 0; nn < CHK; nn++) {
                            float4 h4 = *(const float4*)(Hb + toks[nn] * DH + c);
                            acc[nn] += dot4(h4, w4);
                        }
                    }
#pragma unroll
                    for (int nn = 0; nn < CHK; nn++)
                        t[toks[nn] * DD + tid] += wt[nn] * (acc[nn] + b2);
                }
            }
            __syncthreads();
        }
    }

    // ======================= final norm + circulant head =======================
    ln_stats(t, 0, 1, sp->m, sp->rs);
    __syncthreads();
    float* cls = Y;  // 192
    cls[tid] = (t[tid] - sp->m[0]) * sp->rs[0] * norm_g[tid] + norm_b[tid];
    __syncthreads();
    float* HH = S;  // 384
    for (int ko = tid; ko < 2 * DD; ko += NTHR) {
        int k = ko / 96, o = ko % 96;
        float acc = hc_b[ko];
#pragma unroll
        for (int j = 0; j < 4; j++) {
            const float* w = hc_w + ((size_t)((k - j) & 3) * 96 + o) * 48;
            const float* xv = cls + j * 48;
#pragma unroll
            for (int c = 0; c < 48; c += 4) {
                float4 w4 = *(const float4*)(w + c);
                float4 x4 = *(const float4*)(xv + c);
                acc += dot4(x4, w4);
            }
        }
        HH[ko] = gelu_exact(acc);
    }
    __syncthreads();
    for (int ci = tid; ci < NCLS; ci += NTHR) {
        const float* w = head_w + (size_t)ci * (2 * DD);
        float acc = head_b[ci];
        for (int c = 0; c < 2 * DD; c += 4) {
            float4 w4 = *(const float4*)(w + c);
            float4 h4 = *(const float4*)(HH + c);
            acc += dot4(h4, w4);
        }
        out[b * NCLS + ci] = acc;
    }
}

extern "C" void kernel_launch(void* const* d_in, const int* in_sizes, int n_in,
                              void* d_out, int out_size) {
    (void)in_sizes; (void)n_in; (void)out_size;
    const float* x          = (const float*)d_in[0];
    const float* conv_w     = (const float*)d_in[1];
    const float* conv_b     = (const float*)d_in[2];
    const float* pe_g       = (const float*)d_in[3];
    const float* pe_b       = (const float*)d_in[4];
    const float* cls_token  = (const float*)d_in[5];
    const float* pos_embed  = (const float*)d_in[6];
    const float* n1_g       = (const float*)d_in[7];
    const float* n1_b       = (const float*)d_in[8];
    const float* qkv_w      = (const float*)d_in[9];
    const float* temp       = (const float*)d_in[10];
    const float* proj_w     = (const float*)d_in[11];
    const float* proj_b     = (const float*)d_in[12];
    const float* n2_g       = (const float*)d_in[13];
    const float* n2_b       = (const float*)d_in[14];
    const float* gate_w     = (const float*)d_in[15];
    const float* gate_b     = (const float*)d_in[16];
    const float* e_w1       = (const float*)d_in[17];
    const float* e_b1       = (const float*)d_in[18];
    const float* e_w2       = (const float*)d_in[19];
    const float* e_b2       = (const float*)d_in[20];
    const float* attn_scale = (const float*)d_in[21];
    const float* mlp_scale  = (const float*)d_in[22];
    const float* norm_g     = (const float*)d_in[23];
    const float* norm_b     = (const float*)d_in[24];
    const float* hc_w       = (const float*)d_in[25];
    const float* hc_b       = (const float*)d_in[26];
    const float* head_w     = (const float*)d_in[27];
    const float* head_b     = (const float*)d_in[28];

    cudaFuncSetAttribute(hypervit_kernel, cudaFuncAttributeMaxDynamicSharedMemorySize,
                         (int)sizeof(SM));
    hypervit_kernel<<<NB, NTHR, sizeof(SM)>>>(
        x, conv_w, conv_b, pe_g, pe_b, cls_token, pos_embed,
        n1_g, n1_b, qkv_w, temp, proj_w, proj_b, n2_g, n2_b,
        gate_w, gate_b, e_w1, e_b1, e_w2, e_b2,
        attn_scale, mlp_scale, norm_g, norm_b, hc_w, hc_b,
        head_w, head_b, (float*)d_out);
}

// round 2
// speedup vs baseline: 1.3952x; 1.3952x over previous
#include <cuda_runtime.h>
#include <math.h>

#define NB 128
#define DD 192
#define DEPTHL 12
#define NHD 3
#define HDIM 64
#define NE 4
#define NT 65
#define NTP 66
#define NCLS 100
#define DH 384
#define NTHR 384
#define NWARP 12
#define CK 34           // MoE chunk rows
#define RH 33           // rows per warp-half for 65/66-row GEMMs

typedef unsigned long long ull;

struct __align__(16) SM {
    float t[NTP * DD];
    float Y[NTP * DD];
    float S[NTP * DH];     // qkv + O; MoE: Yc (CK*DD) then Hc (CK*DH)
    float m[NTP];
    float rs[NTP];
    float gl[NTP * NE];
    float selw[NTP * 2];
    float ewt[NE * 72];
    int   seli[NTP * 2];
    int   elist[NE * 72];
    int   ecnt[NE];
};

__device__ __forceinline__ ull fma2(ull a, ull b, ull c) {
    ull d;
    asm("fma.rn.f32x2 %0, %1, %2, %3;" : "=l"(d) : "l"(a), "l"(b), "l"(c));
    return d;
}
__device__ __forceinline__ float f2sum(ull v) {
    float lo = __uint_as_float((unsigned)(v & 0xffffffffull));
    float hi = __uint_as_float((unsigned)(v >> 32));
    return lo + hi;
}

__device__ __forceinline__ float gelu_exact(float x) {
    return 0.5f * x * (1.0f + erff(x * 0.70710678118654752f));
}

__device__ __forceinline__ float dot4(float4 a, float4 b) {
    return a.x * b.x + a.y * b.y + a.z * b.z + a.w * b.w;
}

__device__ __forceinline__ void ln_stats(const float* __restrict__ base, int n0, int n1,
                                         float* __restrict__ m, float* __restrict__ rs) {
    int warp = threadIdx.x >> 5, lane = threadIdx.x & 31;
    for (int n = n0 + warp; n < n1; n += NWARP) {
        const float* row = base + n * DD;
        float s = 0.f;
        for (int c = lane; c < DD; c += 32) s += row[c];
#pragma unroll
        for (int o = 16; o; o >>= 1) s += __shfl_xor_sync(0xffffffffu, s, o);
        float mm = s * (1.0f / DD);
        float q = 0.f;
        for (int c = lane; c < DD; c += 32) { float d = row[c] - mm; q += d * d; }
#pragma unroll
        for (int o = 16; o; o >>= 1) q += __shfl_xor_sync(0xffffffffu, q, o);
        if (lane == 0) { m[n] = mm; rs[n] = rsqrtf(q * (1.0f / DD) + 1e-5f); }
    }
}

__global__ void __launch_bounds__(NTHR, 1) hypervit_kernel(
    const float* __restrict__ x, const float* __restrict__ conv_w, const float* __restrict__ conv_b,
    const float* __restrict__ pe_g, const float* __restrict__ pe_b,
    const float* __restrict__ cls_token, const float* __restrict__ pos_embed,
    const float* __restrict__ n1_g, const float* __restrict__ n1_b,
    const float* __restrict__ qkv_w, const float* __restrict__ temp,
    const float* __restrict__ proj_w, const float* __restrict__ proj_b,
    const float* __restrict__ n2_g, const float* __restrict__ n2_b,
    const float* __restrict__ gate_w, const float* __restrict__ gate_b,
    const float* __restrict__ e_w1, const float* __restrict__ e_b1,
    const float* __restrict__ e_w2, const float* __restrict__ e_b2,
    const float* __restrict__ attn_scale, const float* __restrict__ mlp_scale,
    const float* __restrict__ norm_g, const float* __restrict__ norm_b,
    const float* __restrict__ hc_w, const float* __restrict__ hc_b,
    const float* __restrict__ head_w, const float* __restrict__ head_b,
    float* __restrict__ out)
{
    extern __shared__ char smraw[];
    SM* sp = (SM*)smraw;
    const int b = blockIdx.x;
    const int tid = threadIdx.x;
    const int warp = tid >> 5, lane = tid & 31;
    float* t = sp->t;
    float* Y = sp->Y;
    float* S = sp->S;
    float* O = S + NTP * DD;

    for (int i = tid; i < NTP * DH; i += NTHR) S[i] = 0.f;

    // ======================= patch embed =======================
    {
        float* P = Y;  // 64 x 48
        for (int i = tid; i < 64 * 48; i += NTHR) {
            int patch = i / 48, f = i % 48;
            int c = f >> 4, pi = (f >> 2) & 3, pj = f & 3;
            int ph = patch >> 3, pw = patch & 7;
            P[i] = x[((b * 3 + c) * 32 + ph * 4 + pi) * 32 + pw * 4 + pj];
        }
        __syncthreads();
        for (int task = tid; task < 64 * DD; task += NTHR) {
            int p = task / DD, c = task % DD;
            const float* w = conv_w + c * 48;
            float acc = conv_b[c];
#pragma unroll
            for (int k = 0; k < 48; k += 4) {
                float4 w4 = *(const float4*)(w + k);
                float4 p4 = *(const float4*)(P + p * 48 + k);
                acc += dot4(p4, w4);
            }
            t[(p + 1) * DD + c] = acc;  // t and Y disjoint buffers
        }
        __syncthreads();
        ln_stats(t, 1, 65, sp->m, sp->rs);
        __syncthreads();
        for (int i = tid; i < 64 * DD; i += NTHR) {
            int n = 1 + i / DD, c = i % DD;
            t[n * DD + c] = (t[n * DD + c] - sp->m[n]) * sp->rs[n] * pe_g[c] + pe_b[c]
                            + pos_embed[n * DD + c];
        }
        for (int c = tid; c < DD; c += NTHR) {
            t[c] = cls_token[c] + pos_embed[c];
            t[65 * DD + c] = 0.f;
        }
    }
    __syncthreads();

    // ======================= transformer layers =======================
    for (int l = 0; l < DEPTHL; l++) {
        // ---- LN1 -> Y ----
        ln_stats(t, 0, 65, sp->m, sp->rs);
        __syncthreads();
        for (int i = tid; i < 65 * DD; i += NTHR) {
            int n = i / DD, c = i % DD;
            Y[i] = (t[i] - sp->m[n]) * sp->rs[n] * n1_g[l * DD + c] + n1_b[l * DD + c];
        }
        for (int c = tid; c < DD; c += NTHR) Y[65 * DD + c] = 0.f;
        __syncthreads();

        const float asc = attn_scale[l];

        // ---- attention, per head ----
        for (int h = 0; h < NHD; h++) {
            // qkv GEMM: col-owner lanes, broadcast Y reads, FFMA2
            {
                int cg = warp >> 1, rh = warp & 1;
                int col = cg * 32 + lane;
                int r0 = rh * RH;
                int sec = col >> 6, d = col & 63;
                const float* w = qkv_w + ((size_t)(l * 3 + sec) * DD + h * HDIM + d) * DD;
                const ulonglong2* wp = (const ulonglong2*)w;
                ull acc[RH];
#pragma unroll
                for (int r = 0; r < RH; r++) acc[r] = 0ull;
                ulonglong2 wv = wp[0];
                const char* ybase = (const char*)(Y + r0 * DD);
                for (int kk = 0; kk < 48; kk++) {
                    ulonglong2 wn;
                    if (kk < 47) wn = wp[kk + 1];
                    const char* yb = ybase + kk * 16;
#pragma unroll
                    for (int r = 0; r < RH; r++) {
                        ulonglong2 yv = *(const ulonglong2*)(yb + r * (DD * 4));
                        acc[r] = fma2(yv.x, wv.x, acc[r]);
                        acc[r] = fma2(yv.y, wv.y, acc[r]);
                    }
                    wv = wn;
                }
#pragma unroll
                for (int r = 0; r < RH; r++) S[(r0 + r) * DD + col] = f2sum(acc[r]);
            }
            __syncthreads();

            // banded attention (|i-j| <= 3)
            {
                float coef = 0.125f / temp[l * NHD + h];
                for (int i = warp; i < 65; i += NWARP) {
                    int jlo = (i - 3 < 0) ? 0 : i - 3;
                    int jhi = (i + 3 > 64) ? 64 : i + 3;
                    int cnt = jhi - jlo + 1;
                    const float* q = S + i * DD;
                    float2 qv = *(const float2*)(q + 2 * lane);
                    float sc[7];
#pragma unroll
                    for (int jj = 0; jj < 7; jj++) {
                        if (jj < cnt) {
                            const float* k = S + (jlo + jj) * DD + 64;
                            float2 kv = *(const float2*)(k + 2 * lane);
                            float p = qv.x * kv.x + qv.y * kv.y;
#pragma unroll
                            for (int o = 16; o; o >>= 1) p += __shfl_xor_sync(0xffffffffu, p, o);
                            sc[jj] = p * coef;
                        }
                    }
                    float mx = sc[0];
#pragma unroll
                    for (int jj = 1; jj < 7; jj++) if (jj < cnt) mx = fmaxf(mx, sc[jj]);
                    float ssum = 0.f;
#pragma unroll
                    for (int jj = 0; jj < 7; jj++) if (jj < cnt) { sc[jj] = expf(sc[jj] - mx); ssum += sc[jj]; }
                    float inv = 1.0f / ssum;
                    float o0 = 0.f, o1 = 0.f;
#pragma unroll
                    for (int jj = 0; jj < 7; jj++) {
                        if (jj < cnt) {
                            const float* v = S + (jlo + jj) * DD + 128;
                            float2 vv = *(const float2*)(v + 2 * lane);
                            o0 += sc[jj] * vv.x;
                            o1 += sc[jj] * vv.y;
                        }
                    }
                    O[i * DD + h * HDIM + 2 * lane]     = o0 * inv;
                    O[i * DD + h * HDIM + 2 * lane + 1] = o1 * inv;
                }
            }
            __syncthreads();
        }

        // ---- proj + residual ----
        {
            int cg = warp >> 1, rh = warp & 1;
            int col = cg * 32 + lane;
            int r0 = rh * RH;
            const float* w = proj_w + ((size_t)l * DD + col) * DD;
            const ulonglong2* wp = (const ulonglong2*)w;
            float pb = proj_b[l * DD + col];
            ull acc[RH];
#pragma unroll
            for (int r = 0; r < RH; r++) acc[r] = 0ull;
            ulonglong2 wv = wp[0];
            const char* obase = (const char*)(O + r0 * DD);
            for (int kk = 0; kk < 48; kk++) {
                ulonglong2 wn;
                if (kk < 47) wn = wp[kk + 1];
                const char* ob = obase + kk * 16;
#pragma unroll
                for (int r = 0; r < RH; r++) {
                    ulonglong2 ov = *(const ulonglong2*)(ob + r * (DD * 4));
                    acc[r] = fma2(ov.x, wv.x, acc[r]);
                    acc[r] = fma2(ov.y, wv.y, acc[r]);
                }
                wv = wn;
            }
#pragma unroll
            for (int r = 0; r < RH; r++)
                t[(r0 + r) * DD + col] += asc * (f2sum(acc[r]) + pb);
        }
        __syncthreads();

        // ---- LN2 -> Y ----
        ln_stats(t, 0, 65, sp->m, sp->rs);
        __syncthreads();
        for (int i = tid; i < 65 * DD; i += NTHR) {
            int n = i / DD, c = i % DD;
            Y[i] = (t[i] - sp->m[n]) * sp->rs[n] * n2_g[l * DD + c] + n2_b[l * DD + c];
        }
        for (int c = tid; c < DD; c += NTHR) Y[65 * DD + c] = 0.f;
        __syncthreads();

        // ---- gating ----
        for (int task = tid; task < NT * NE; task += NTHR) {
            int n = task >> 2, e = task & 3;
            const float* gw = gate_w + ((size_t)l * NE + e) * DD;
            float acc = gate_b[l * NE + e];
            for (int c = 0; c < DD; c += 4) {
                float4 y4 = *(const float4*)(Y + n * DD + c);
                float4 w4 = *(const float4*)(gw + c);
                acc += dot4(y4, w4);
            }
            sp->gl[n * NE + e] = acc;
        }
        __syncthreads();
        if (tid < NT) {
            float vv[4] = { sp->gl[tid * 4 + 0], sp->gl[tid * 4 + 1],
                            sp->gl[tid * 4 + 2], sp->gl[tid * 4 + 3] };
            int i0 = 0; float bmax = vv[0];
#pragma unroll
            for (int e = 1; e < 4; e++) if (vv[e] > bmax) { bmax = vv[e]; i0 = e; }
            int i1 = -1; float b2v = -1e30f;
#pragma unroll
            for (int e = 0; e < 4; e++) if (e != i0 && vv[e] > b2v) { b2v = vv[e]; i1 = e; }
            float w1 = expf(b2v - bmax);
            float inv = 1.0f / (1.0f + w1);
            sp->seli[tid * 2 + 0] = i0;
            sp->seli[tid * 2 + 1] = i1;
            sp->selw[tid * 2 + 0] = inv;
            sp->selw[tid * 2 + 1] = w1 * inv;
        }
        __syncthreads();
        if (tid == 0) {
            float msc = mlp_scale[l];
            int cnt[4] = { 0, 0, 0, 0 };
            for (int n = 0; n < NT; n++) {
                for (int sidx = 0; sidx < 2; sidx++) {
                    int e = sp->seli[n * 2 + sidx];
                    sp->elist[e * 72 + cnt[e]] = n;
                    sp->ewt[e * 72 + cnt[e]] = sp->selw[n * 2 + sidx] * msc;
                    cnt[e]++;
                }
            }
            for (int e = 0; e < 4; e++) {
                while (cnt[e] % CK != 0) {
                    sp->elist[e * 72 + cnt[e]] = 65;   // dummy row
                    sp->ewt[e * 72 + cnt[e]] = 0.f;
                    cnt[e]++;
                }
                sp->ecnt[e] = cnt[e];
            }
        }
        __syncthreads();

        // ---- expert FFNs (token-grouped, chunked) ----
        float* Yc = S;             // CK x DD
        float* Hc = S + CK * DD;   // CK x DH
        for (int e = 0; e < NE; e++) {
            int cnt = sp->ecnt[e];
            int nch = cnt / CK;
            for (int ch = 0; ch < nch; ch++) {
                // gather chunk rows
                for (int i = tid; i < CK * DD; i += NTHR) {
                    int r = i / DD, c = i % DD;
                    int tok = sp->elist[e * 72 + ch * CK + r];
                    Yc[i] = Y[tok * DD + c];
                }
                __syncthreads();
                // GEMM1: [CK][DH] = Yc @ w1^T, gelu
                {
                    int col = warp * 32 + lane;  // 0..383
                    const float* w = e_w1 + ((size_t)(l * NE + e) * DH + col) * DD;
                    const ulonglong2* wp = (const ulonglong2*)w;
                    float bias = e_b1[(size_t)(l * NE + e) * DH + col];
                    ull acc[CK];
#pragma unroll
                    for (int r = 0; r < CK; r++) acc[r] = 0ull;
                    ulonglong2 wv = wp[0];
                    for (int kk = 0; kk < 48; kk++) {
                        ulonglong2 wn;
                        if (kk < 47) wn = wp[kk + 1];
                        const char* yb = (const char*)Yc + kk * 16;
#pragma unroll
                        for (int r = 0; r < CK; r++) {
                            ulonglong2 yv = *(const ulonglong2*)(yb + r * (DD * 4));
                            acc[r] = fma2(yv.x, wv.x, acc[r]);
                            acc[r] = fma2(yv.y, wv.y, acc[r]);
                        }
                        wv = wn;
                    }
#pragma unroll
                    for (int r = 0; r < CK; r++)
                        Hc[r * DH + col] = gelu_exact(f2sum(acc[r]) + bias);
                }
                __syncthreads();
                // GEMM2: scatter += into t
                {
                    int cg = warp >> 1, rh = warp & 1;
                    int col = cg * 32 + lane;
                    int r0 = rh * 17;
                    const float* w = e_w2 + ((size_t)(l * NE + e) * DD + col) * DH;
                    const ulonglong2* wp = (const ulonglong2*)w;
                    float b2 = e_b2[(size_t)(l * NE + e) * DD + col];
                    ull acc[17];
#pragma unroll
                    for (int r = 0; r < 17; r++) acc[r] = 0ull;
                    ulonglong2 wv = wp[0];
                    const char* hbase = (const char*)(Hc + r0 * DH);
                    for (int kk = 0; kk < 96; kk++) {
                        ulonglong2 wn;
                        if (kk < 95) wn = wp[kk + 1];
                        const char* hb = hbase + kk * 16;
#pragma unroll
                        for (int r = 0; r < 17; r++) {
                            ulonglong2 hv = *(const ulonglong2*)(hb + r * (DH * 4));
                            acc[r] = fma2(hv.x, wv.x, acc[r]);
                            acc[r] = fma2(hv.y, wv.y, acc[r]);
                        }
                        wv = wn;
                    }
                    int idx0 = e * 72 + ch * CK + r0;
#pragma unroll
                    for (int r = 0; r < 17; r++) {
                        int tok = sp->elist[idx0 + r];
                        float wt = sp->ewt[idx0 + r];
                        t[tok * DD + col] += wt * (f2sum(acc[r]) + b2);
                    }
                }
                __syncthreads();
            }
        }
    }

    // ======================= final norm + circulant head =======================
    ln_stats(t, 0, 1, sp->m, sp->rs);
    __syncthreads();
    float* cls = Y;
    for (int c = tid; c < DD; c += NTHR)
        cls[c] = (t[c] - sp->m[0]) * sp->rs[0] * norm_g[c] + norm_b[c];
    __syncthreads();
    float* HH = S;
    for (int ko = tid; ko < 2 * DD; ko += NTHR) {
        int k = ko / 96, o = ko % 96;
        float acc = hc_b[ko];
#pragma unroll
        for (int j = 0; j < 4; j++) {
            const float* w = hc_w + ((size_t)((k - j) & 3) * 96 + o) * 48;
            const float* xv = cls + j * 48;
#pragma unroll
            for (int c = 0; c < 48; c += 4) {
                float4 w4 = *(const float4*)(w + c);
                float4 x4 = *(const float4*)(xv + c);
                acc += dot4(x4, w4);
            }
        }
        HH[ko] = gelu_exact(acc);
    }
    __syncthreads();
    for (int ci = tid; ci < NCLS; ci += NTHR) {
        const float* w = head_w + (size_t)ci * (2 * DD);
        float acc = head_b[ci];
        for (int c = 0; c < 2 * DD; c += 4) {
            float4 w4 = *(const float4*)(w + c);
            float4 h4 = *(const float4*)(HH + c);
            acc += dot4(h4, w4);
        }
        out[b * NCLS + ci] = acc;
    }
}

extern "C" void kernel_launch(void* const* d_in, const int* in_sizes, int n_in,
                              void* d_out, int out_size) {
    (void)in_sizes; (void)n_in; (void)out_size;
    const float* x          = (const float*)d_in[0];
    const float* conv_w     = (const float*)d_in[1];
    const float* conv_b     = (const float*)d_in[2];
    const float* pe_g       = (const float*)d_in[3];
    const float* pe_b       = (const float*)d_in[4];
    const float* cls_token  = (const float*)d_in[5];
    const float* pos_embed  = (const float*)d_in[6];
    const float* n1_g       = (const float*)d_in[7];
    const float* n1_b       = (const float*)d_in[8];
    const float* qkv_w      = (const float*)d_in[9];
    const float* temp       = (const float*)d_in[10];
    const float* proj_w     = (const float*)d_in[11];
    const float* proj_b     = (const float*)d_in[12];
    const float* n2_g       = (const float*)d_in[13];
    const float* n2_b       = (const float*)d_in[14];
    const float* gate_w     = (const float*)d_in[15];
    const float* gate_b     = (const float*)d_in[16];
    const float* e_w1       = (const float*)d_in[17];
    const float* e_b1       = (const float*)d_in[18];
    const float* e_w2       = (const float*)d_in[19];
    const float* e_b2       = (const float*)d_in[20];
    const float* attn_scale = (const float*)d_in[21];
    const float* mlp_scale  = (const float*)d_in[22];
    const float* norm_g     = (const float*)d_in[23];
    const float* norm_b     = (const float*)d_in[24];
    const float* hc_w       = (const float*)d_in[25];
    const float* hc_b       = (const float*)d_in[26];
    const float* head_w     = (const float*)d_in[27];
    const float* head_b     = (const float*)d_in[28];

    cudaFuncSetAttribute(hypervit_kernel, cudaFuncAttributeMaxDynamicSharedMemorySize,
                         (int)sizeof(SM));
    hypervit_kernel<<<NB, NTHR, sizeof(SM)>>>(
        x, conv_w, conv_b, pe_g, pe_b, cls_token, pos_embed,
        n1_g, n1_b, qkv_w, temp, proj_w, proj_b, n2_g, n2_b,
        gate_w, gate_b, e_w1, e_b1, e_w2, e_b2,
        attn_scale, mlp_scale, norm_g, norm_b, hc_w, hc_b,
        head_w, head_b, (float*)d_out);
}